// round 3
// baseline (speedup 1.0000x reference)
#include <cuda_runtime.h>
#include <cuda_bf16.h>

// Retrace loss via suffix scan of affine transforms, persistent blocks with
// software-pipelined row prefetch.
//
// Per row (length 1024 after dropping last col):
//   j < 1023:  b[j] = g*clip(tp[j+2]/bp[j+2], eps, 1)
//              a[j] = rw[j+1] + g*eQ[j+2] - b[j]*tQ[j+2]
//   j == 1023: identity (0,1)
//   Q_ret[j] = a[j] + b[j]*Q_ret[j+1],   Q_ret past end = Q[1024]
//   out = mean (Q[j]-Q_ret[j])^2 over (4096,1024)
//
// 256 threads/block, ROWS_PER_BLOCK=8 contiguous rows/block, grid=512 (single
// wave). Next row's loads are issued before the current row's scan barriers so
// DRAM streams continuously.

#define GAMMA  0.99f
#define TLEN   1024
#define STRIDE 1025
#define RPB    8      // rows per block
#define NBLK   512    // 4096 / RPB

__global__ void zero_out_kernel(float* out) { out[0] = 0.0f; }

struct RowRegs {
    float a[4], b[4], Qj[4], Qlast;
};

__device__ __forceinline__
void load_row(const float* __restrict__ Q,  const float* __restrict__ eQ,
              const float* __restrict__ tQ, const float* __restrict__ rw,
              const float* __restrict__ tp, const float* __restrict__ bp,
              long base, int t, RowRegs& R) {
    R.Qlast = __ldg(&Q[base + TLEN]);
    #pragma unroll
    for (int s = 0; s < 4; s++) {
        const int j = (s << 8) + t;
        R.Qj[s] = Q[base + j];
        if (j < TLEN - 1) {
            const float r  = rw[base + j + 1];
            const float e  = eQ[base + j + 2];
            const float tq = tQ[base + j + 2];
            float c = tp[base + j + 2] / bp[base + j + 2];
            c = fminf(fmaxf(c, 1e-10f), 1.0f);
            R.b[s] = GAMMA * c;
            R.a[s] = fmaf(GAMMA, e, r) - R.b[s] * tq;
        } else {            // j == 1023: identity transform
            R.a[s] = 0.0f;
            R.b[s] = 1.0f;
        }
    }
}

__global__ __launch_bounds__(256, 4)
void retrace_kernel(const float* __restrict__ Q,
                    const float* __restrict__ eQ,
                    const float* __restrict__ tQ,
                    const float* __restrict__ rw,
                    const float* __restrict__ tp,
                    const float* __restrict__ bp,
                    float* __restrict__ out,
                    int B) {
    const int t    = threadIdx.x;
    const int lane = t & 31;
    const int warp = t >> 5;             // 0..7

    __shared__ float cA[32], cB[32];     // chunk aggregates (c = s*8 + warp)
    __shared__ float iA[33], iB[33];     // inclusive chunk suffixes (+identity)

    const int  row0 = blockIdx.x * RPB;
    float sq = 0.0f;                     // per-thread loss accumulator (all rows)

    RowRegs cur;
    load_row(Q, eQ, tQ, rw, tp, bp, (long)row0 * STRIDE, t, cur);

    #pragma unroll 1
    for (int i = 0; i < RPB; i++) {
        // working copy of this row; then immediately kick off next row's loads
        float a0=cur.a[0], a1=cur.a[1], a2=cur.a[2], a3=cur.a[3];
        float b0=cur.b[0], b1=cur.b[1], b2=cur.b[2], b3=cur.b[3];
        float q0=cur.Qj[0], q1=cur.Qj[1], q2=cur.Qj[2], q3=cur.Qj[3];
        float ql=cur.Qlast;

        if (i + 1 < RPB)
            load_row(Q, eQ, tQ, rw, tp, bp, (long)(row0 + i + 1) * STRIDE, t, cur);

        // ---- level 1: 4 independent warp suffix scans (ILP across segments) --
        #pragma unroll
        for (int d = 1; d < 32; d <<= 1) {
            float oA0 = __shfl_down_sync(0xffffffffu, a0, d);
            float oB0 = __shfl_down_sync(0xffffffffu, b0, d);
            float oA1 = __shfl_down_sync(0xffffffffu, a1, d);
            float oB1 = __shfl_down_sync(0xffffffffu, b1, d);
            float oA2 = __shfl_down_sync(0xffffffffu, a2, d);
            float oB2 = __shfl_down_sync(0xffffffffu, b2, d);
            float oA3 = __shfl_down_sync(0xffffffffu, a3, d);
            float oB3 = __shfl_down_sync(0xffffffffu, b3, d);
            if (lane + d < 32) {
                a0 = fmaf(b0, oA0, a0); b0 *= oB0;
                a1 = fmaf(b1, oA1, a1); b1 *= oB1;
                a2 = fmaf(b2, oA2, a2); b2 *= oB2;
                a3 = fmaf(b3, oA3, a3); b3 *= oB3;
            }
        }

        if (lane == 0) {
            cA[warp]      = a0; cB[warp]      = b0;
            cA[8 + warp]  = a1; cB[8 + warp]  = b1;
            cA[16 + warp] = a2; cB[16 + warp] = b2;
            cA[24 + warp] = a3; cB[24 + warp] = b3;
        }
        __syncthreads();

        // ---- level 2: one warp scans the 32 chunk aggregates ----
        if (warp == 0) {
            float wA = cA[lane], wB = cB[lane];
            #pragma unroll
            for (int d = 1; d < 32; d <<= 1) {
                float oA = __shfl_down_sync(0xffffffffu, wA, d);
                float oB = __shfl_down_sync(0xffffffffu, wB, d);
                if (lane + d < 32) {
                    wA = fmaf(wB, oA, wA);
                    wB = wB * oB;
                }
            }
            iA[lane] = wA; iB[lane] = wB;
            if (lane == 0) { iA[32] = 0.0f; iB[32] = 1.0f; }
        }
        __syncthreads();

        // ---- apply + accumulate squared error ----
        {
            const float x0 = fmaf(iB[warp + 1],      ql, iA[warp + 1]);
            const float x1 = fmaf(iB[8 + warp + 1],  ql, iA[8 + warp + 1]);
            const float x2 = fmaf(iB[16 + warp + 1], ql, iA[16 + warp + 1]);
            const float x3 = fmaf(iB[24 + warp + 1], ql, iA[24 + warp + 1]);
            float d0 = q0 - fmaf(b0, x0, a0);
            float d1 = q1 - fmaf(b1, x1, a1);
            float d2 = q2 - fmaf(b2, x2, a2);
            float d3 = q3 - fmaf(b3, x3, a3);
            sq = fmaf(d0, d0, sq);
            sq = fmaf(d1, d1, sq);
            sq = fmaf(d2, d2, sq);
            sq = fmaf(d3, d3, sq);
        }
        // next iteration's cA/cB writes are ordered by the syncthreads above
        // on its level-1 completion path; iA/iB reads here precede warp0's
        // next write which sits behind the next __syncthreads.
        __syncthreads();
    }

    // ---- one block reduction for all RPB rows ----
    #pragma unroll
    for (int d = 16; d > 0; d >>= 1)
        sq += __shfl_xor_sync(0xffffffffu, sq, d);

    __shared__ float red[8];
    if (lane == 0) red[warp] = sq;
    __syncthreads();
    if (warp == 0) {
        float v = (lane < 8) ? red[lane] : 0.0f;
        #pragma unroll
        for (int d = 4; d > 0; d >>= 1)
            v += __shfl_xor_sync(0xffffffffu, v, d);
        if (lane == 0)
            atomicAdd(out, v * (1.0f / ((float)B * (float)TLEN)));
    }
}

extern "C" void kernel_launch(void* const* d_in, const int* in_sizes, int n_in,
                              void* d_out, int out_size) {
    const float* Q  = (const float*)d_in[0];
    const float* eQ = (const float*)d_in[1];
    const float* tQ = (const float*)d_in[2];
    const float* rw = (const float*)d_in[3];
    const float* tp = (const float*)d_in[4];
    const float* bp = (const float*)d_in[5];
    float* out = (float*)d_out;

    const int B = in_sizes[0] / STRIDE;   // 4096

    zero_out_kernel<<<1, 1>>>(out);
    retrace_kernel<<<NBLK, 256>>>(Q, eQ, tQ, rw, tp, bp, out, B);
}

// round 6
// speedup vs baseline: 1.2604x; 1.2604x over previous
#include <cuda_runtime.h>
#include <cuda_bf16.h>
#include <cstdint>

// Retrace loss via suffix scan of affine transforms.
// 16B cp.async (LDGSTS) ping-pong pipeline into STATIC shared memory
// (41.1KB < 48KB default; no cudaFuncSetAttribute, no dynamic smem).
// Q is NOT staged: it is consumed pointwise at the apply step, so a plain
// coalesced LDG issued right after the stage barrier hides fully behind the
// scan phase.
//
//   j < 1023:  b[j] = g*clip(tp[j+2]/bp[j+2], eps, 1)
//              a[j] = rw[j+1] + g*eQ[j+2] - b[j]*tQ[j+2]
//   j == 1023: identity (0,1)
//   Q_ret[j] = a[j] + b[j]*Q_ret[j+1],  Q_ret past end = Q[1024]
//   out = mean (Q[j]-Q_ret[j])^2 over (4096,1024)
//
// Row stride 1025 floats => row r base has float alignment shift = r & 3.
// Each staged array copies the 16B-aligned superset [base-shift, +1028)
// (257 vec4 LDGSTS) and is read at j+shift. Row 4095 (shift=3) ends exactly
// at the array end -> no OOB.
//
// 256 threads/CTA, RPB=8 rows/CTA, grid=512 -> single resident wave.

#define GAMMA  0.99f
#define TLEN   1024
#define STRIDE 1025
#define RPB    8
#define APAD   1028                    // aligned padded row floats per array
#define NARR   5                       // staged arrays: eQ,tQ,rw,tp,bp
#define STAGE_FLOATS (NARR * APAD)

__global__ void zero_out_kernel(float* out) { out[0] = 0.0f; }

__device__ __forceinline__ void cp16(uint32_t saddr, const float* g) {
    asm volatile("cp.async.cg.shared.global [%0], [%1], 16;"
                 :: "r"(saddr), "l"(g));
}
__device__ __forceinline__ void cp_commit() {
    asm volatile("cp.async.commit_group;");
}
__device__ __forceinline__ void cp_wait1() {
    asm volatile("cp.async.wait_group 1;");
}
__device__ __forceinline__ void cp_wait0() {
    asm volatile("cp.async.wait_group 0;");
}

__global__ __launch_bounds__(256)
void retrace_kernel(const float* __restrict__ Q,
                    const float* __restrict__ eQ,
                    const float* __restrict__ tQ,
                    const float* __restrict__ rw,
                    const float* __restrict__ tp,
                    const float* __restrict__ bp,
                    float* __restrict__ out,
                    int B) {
    __shared__ __align__(16) float sbuf[2][STAGE_FLOATS];  // 41120 B
    __shared__ float cA[32], cB[32];   // chunk aggregates (c = s*8 + warp)
    __shared__ float iA[33], iB[33];   // inclusive chunk suffixes (+identity)
    __shared__ float red[8];

    const int t    = threadIdx.x;
    const int lane = t & 31;
    const int warp = t >> 5;           // 0..7
    const int row0 = blockIdx.x * RPB;

    // ---- issue one row's async copies into stage p (16B aligned vec4) ----
    auto issue_row = [&](int row, int p) {
        const int  shift = row & 3;                      // float misalignment
        const long gal   = (long)row * STRIDE - shift;   // 16B-aligned index
        float* stage = sbuf[p];
        #pragma unroll
        for (int arr = 0; arr < NARR; arr++) {
            const float* src =
                (arr == 0 ? eQ : arr == 1 ? tQ : arr == 2 ? rw :
                 arr == 3 ? tp : bp) + gal;
            float* dst = stage + arr * APAD;
            // 257 vec4 per array: thread t does k=t, thread 0 also k=256
            cp16((uint32_t)__cvta_generic_to_shared(dst + 4 * t), src + 4 * t);
            if (t == 0)
                cp16((uint32_t)__cvta_generic_to_shared(dst + 4 * 256),
                     src + 4 * 256);
        }
        cp_commit();
    };

    float sq = 0.0f;

    issue_row(row0, 0);                // prologue

    #pragma unroll 1
    for (int i = 0; i < RPB; i++) {
        const int  p     = i & 1;
        const int  row   = row0 + i;
        const int  shift = row & 3;
        const long gb    = (long)row * STRIDE;

        if (i + 1 < RPB) { issue_row(row + 1, p ^ 1); cp_wait1(); }
        else             { cp_wait0(); }
        __syncthreads();               // stage p fully visible

        // Q direct from gmem — consumed only at the apply step (~900 cyc away)
        const float q0 = Q[gb + t];
        const float q1 = Q[gb + t + 256];
        const float q2 = Q[gb + t + 512];
        const float q3 = Q[gb + t + 768];
        const float ql = __ldg(&Q[gb + TLEN]);

        const float* bE = sbuf[p] + shift;
        const float* bT = bE + APAD;
        const float* bR = bE + 2 * APAD;
        const float* bP = bE + 3 * APAD;
        const float* bB = bE + 4 * APAD;

        float a0, a1, a2, a3, b0, b1, b2, b3;
        {
            int j = t;                                   // s=0, j < 1023
            { float c = fminf(fmaxf(bP[j+2] / bB[j+2], 1e-10f), 1.0f);
              b0 = GAMMA * c;
              a0 = fmaf(GAMMA, bE[j+2], bR[j+1]) - b0 * bT[j+2]; }
            j += 256;                                    // s=1
            { float c = fminf(fmaxf(bP[j+2] / bB[j+2], 1e-10f), 1.0f);
              b1 = GAMMA * c;
              a1 = fmaf(GAMMA, bE[j+2], bR[j+1]) - b1 * bT[j+2]; }
            j += 256;                                    // s=2
            { float c = fminf(fmaxf(bP[j+2] / bB[j+2], 1e-10f), 1.0f);
              b2 = GAMMA * c;
              a2 = fmaf(GAMMA, bE[j+2], bR[j+1]) - b2 * bT[j+2]; }
            j += 256;                                    // s=3
            if (j < TLEN - 1) {
                float c = fminf(fmaxf(bP[j+2] / bB[j+2], 1e-10f), 1.0f);
                b3 = GAMMA * c;
                a3 = fmaf(GAMMA, bE[j+2], bR[j+1]) - b3 * bT[j+2];
            } else { a3 = 0.0f; b3 = 1.0f; }             // j==1023: identity
        }

        // ---- level 1: 4 independent warp suffix scans (ILP across segs) ----
        #pragma unroll
        for (int d = 1; d < 32; d <<= 1) {
            float oA0 = __shfl_down_sync(0xffffffffu, a0, d);
            float oB0 = __shfl_down_sync(0xffffffffu, b0, d);
            float oA1 = __shfl_down_sync(0xffffffffu, a1, d);
            float oB1 = __shfl_down_sync(0xffffffffu, b1, d);
            float oA2 = __shfl_down_sync(0xffffffffu, a2, d);
            float oB2 = __shfl_down_sync(0xffffffffu, b2, d);
            float oA3 = __shfl_down_sync(0xffffffffu, a3, d);
            float oB3 = __shfl_down_sync(0xffffffffu, b3, d);
            if (lane + d < 32) {
                a0 = fmaf(b0, oA0, a0); b0 *= oB0;
                a1 = fmaf(b1, oA1, a1); b1 *= oB1;
                a2 = fmaf(b2, oA2, a2); b2 *= oB2;
                a3 = fmaf(b3, oA3, a3); b3 *= oB3;
            }
        }

        if (lane == 0) {
            cA[warp]      = a0; cB[warp]      = b0;
            cA[8 + warp]  = a1; cB[8 + warp]  = b1;
            cA[16 + warp] = a2; cB[16 + warp] = b2;
            cA[24 + warp] = a3; cB[24 + warp] = b3;
        }
        __syncthreads();

        // ---- level 2: one warp scans the 32 chunk aggregates ----
        if (warp == 0) {
            float wA = cA[lane], wB = cB[lane];
            #pragma unroll
            for (int d = 1; d < 32; d <<= 1) {
                float oA = __shfl_down_sync(0xffffffffu, wA, d);
                float oB = __shfl_down_sync(0xffffffffu, wB, d);
                if (lane + d < 32) {
                    wA = fmaf(wB, oA, wA);
                    wB = wB * oB;
                }
            }
            iA[lane] = wA; iB[lane] = wB;
            if (lane == 0) { iA[32] = 0.0f; iB[32] = 1.0f; }
        }
        __syncthreads();

        // ---- apply + accumulate squared error ----
        {
            const float x0 = fmaf(iB[warp + 1],      ql, iA[warp + 1]);
            const float x1 = fmaf(iB[8 + warp + 1],  ql, iA[8 + warp + 1]);
            const float x2 = fmaf(iB[16 + warp + 1], ql, iA[16 + warp + 1]);
            const float x3 = fmaf(iB[24 + warp + 1], ql, iA[24 + warp + 1]);
            float d0 = q0 - fmaf(b0, x0, a0);
            float d1 = q1 - fmaf(b1, x1, a1);
            float d2 = q2 - fmaf(b2, x2, a2);
            float d3 = q3 - fmaf(b3, x3, a3);
            sq = fmaf(d0, d0, sq);
            sq = fmaf(d1, d1, sq);
            sq = fmaf(d2, d2, sq);
            sq = fmaf(d3, d3, sq);
        }
        __syncthreads();   // stage p reads done; safe to overwrite next iter
    }

    // ---- one block reduction for all rows ----
    #pragma unroll
    for (int d = 16; d > 0; d >>= 1)
        sq += __shfl_xor_sync(0xffffffffu, sq, d);

    if (lane == 0) red[warp] = sq;
    __syncthreads();
    if (warp == 0) {
        float v = (lane < 8) ? red[lane] : 0.0f;
        #pragma unroll
        for (int d = 4; d > 0; d >>= 1)
            v += __shfl_xor_sync(0xffffffffu, v, d);
        if (lane == 0)
            atomicAdd(out, v * (1.0f / ((float)B * (float)TLEN)));
    }
}

extern "C" void kernel_launch(void* const* d_in, const int* in_sizes, int n_in,
                              void* d_out, int out_size) {
    const float* Q  = (const float*)d_in[0];
    const float* eQ = (const float*)d_in[1];
    const float* tQ = (const float*)d_in[2];
    const float* rw = (const float*)d_in[3];
    const float* tp = (const float*)d_in[4];
    const float* bp = (const float*)d_in[5];
    float* out = (float*)d_out;

    const int B    = in_sizes[0] / STRIDE;   // 4096
    const int grid = B / RPB;                // 512

    zero_out_kernel<<<1, 1>>>(out);
    retrace_kernel<<<grid, 256>>>(Q, eQ, tQ, rw, tp, bp, out, B);
}